// round 8
// baseline (speedup 1.0000x reference)
#include <cuda_runtime.h>

// ---------------------------------------------------------------------------
// GNNMLP fused kernel, round 6.
//   conv: R4's dup-layout idiom (verified clean fma count), 2 groups/warp
//   MLP:  batched over 4 groups (ring), weights streamed from __device__
//         scratch (prep kernel builds interleaved layout), head from regs
//   16 warps / 512 threads, smem 217KB, all hot-loop addresses base+imm
// ---------------------------------------------------------------------------

#define G_TOT   131072
#define THREADS 512
#define WARPS   16

typedef unsigned long long ull;

__device__ float g_wk[8 * 4096];  // interleaved: Wn1,Wn2,MW1t0,MW1t1,MW2t0,MW2t1,MW3t0,MW3t1

// ---- helpers ---------------------------------------------------------------
__device__ __forceinline__ float2 upk(ull v) {
    float2 r; asm("mov.b64 {%0,%1}, %2;" : "=f"(r.x), "=f"(r.y) : "l"(v)); return r;
}
__device__ __forceinline__ ull f2fma(ull a, ull b, ull c) {
    ull d; asm("fma.rn.f32x2 %0, %1, %2, %3;" : "=l"(d) : "l"(a), "l"(b), "l"(c));
    return d;
}
__device__ __forceinline__ ull f2add(ull a, ull b) {
    ull d; asm("add.rn.f32x2 %0, %1, %2;" : "=l"(d) : "l"(a), "l"(b)); return d;
}
__device__ __forceinline__ void lds128(ull& a, ull& b, unsigned addr) {
    asm volatile("ld.shared.v2.u64 {%0,%1}, [%2];" : "=l"(a), "=l"(b) : "r"(addr));
}
__device__ __forceinline__ void sts128(unsigned a, float x, float y, float z, float w) {
    asm volatile("st.shared.v4.f32 [%0], {%1,%2,%3,%4};"
                 :: "r"(a), "f"(x), "f"(y), "f"(z), "f"(w));
}
__device__ __forceinline__ void ldg2u64(ull& a, ull& b, const float* p) {
    asm volatile("ld.global.nc.v2.u64 {%0,%1}, [%2];" : "=l"(a), "=l"(b) : "l"(p));
}

// ---- SMEM layout (float offsets) ------------------------------------------
// Interleaved weight layout: float4 j=(kh*32+cp) =
//   (W[2kh][2cp], W[2kh][2cp+1], W[2kh+1][2cp], W[2kh+1][2cp+1])
#define OFF_WP1  0
#define OFF_WS1  4096
#define OFF_WP2  8192
#define OFF_WS2  12288
#define OFF_MISC 16384
//  MISC: +0 bp1 +64 b1 +128 bp2 +192 b2 +256 Mb1[128] +384 Mb2[128]
//        +512 Mb3[128] +640 MW4[2][64][2] +896 Mb4[4]
#define OFF_WS_  17408
#define WARP_WS  2304     // OBS dup [12][128] =1536 | NB dup [2][128]=256 | RES dup [4][128]=512
#define SMEM_FLOATS (OFF_WS_ + WARPS * WARP_WS)   // 54272
#define SMEM_BYTES  (SMEM_FLOATS * 4)             // 217088 < 232448

struct Params {
    const float *obs, *Wp1, *bp1, *Ws1, *Wn1, *b1;
    const float *Wp2, *bp2, *Ws2, *Wn2, *b2;
    const float *MW1, *Mb1, *MW2, *Mb2, *MW3, *Mb3, *MW4, *Mb4;
    float *out;
    int ch4;
};

extern __shared__ float smem[];

__device__ __forceinline__ void cp4(float* dst, const float* src, int n) {
    for (int i = threadIdx.x; i < (n >> 2); i += THREADS)
        ((float4*)dst)[i] = ((const float4*)src)[i];
}
// interleave one 64x64 row-major matrix into dst (smem)
__device__ __forceinline__ void cp_i(float* dst, const float* src) {
    const float2* s2 = (const float2*)src;
    float4* d4 = (float4*)dst;
    for (int j = threadIdx.x; j < 1024; j += THREADS) {
        int kh = j >> 5, cp = j & 31;
        float2 a = s2[(2 * kh) * 32 + cp];
        float2 b = s2[(2 * kh + 1) * 32 + cp];
        d4[j] = make_float4(a.x, a.y, b.x, b.y);
    }
}

// ---- prep kernel: interleaved copies of Wn1,Wn2,MW1,MW2,MW3 into g_wk ------
__global__ void prep_kernel(const float* Wn1, const float* Wn2, const float* MW1,
                            const float* MW2, const float* MW3)
{
    int j = blockIdx.x * blockDim.x + threadIdx.x;
    if (j >= 8 * 1024) return;
    int m = j >> 10, e = j & 1023;
    int kh = e >> 5, cp = e & 31;
    const float* src;
    switch (m) {
        case 0: src = Wn1; break;
        case 1: src = Wn2; break;
        case 2: src = MW1; break;
        case 3: src = MW1 + 4096; break;
        case 4: src = MW2; break;
        case 5: src = MW2 + 4096; break;
        case 6: src = MW3; break;
        default: src = MW3 + 4096; break;
    }
    const float2* s2 = (const float2*)src;
    float2 a = s2[(2 * kh) * 32 + cp];
    float2 b = s2[(2 * kh + 1) * 32 + cp];
    ((float4*)(g_wk + m * 4096))[e] = make_float4(a.x, a.y, b.x, b.y);
}

// ---- one SAGE-pool conv, 2 groups (12 dup rows) ----------------------------
// ROWS: dup [12][128fl], row r at +r*512B, k-pair kh at +kh*16B.
// Lane owns output cols {2l, 2l+1}.
template<bool FIRST>
__device__ __forceinline__ void conv2g(unsigned ROWS, unsigned NB, unsigned RESs,
                                       unsigned WPA, unsigned WSA,
                                       const float* __restrict__ wng,
                                       const float* misc, int bP, int bB, int lane)
{
    ull aP[12], aS[12];
    ull bpv = *(const ull*)(misc + bP + 2 * lane);
    #pragma unroll
    for (int r = 0; r < 12; r++) { aP[r] = bpv; aS[r] = 0ull; }

    const unsigned wp = WPA + lane * 16, ws = WSA + lane * 16;
    #pragma unroll 4
    for (int kh = 0; kh < 32; kh++) {
        ull wp0, wp1, ws0, ws1;
        lds128(wp0, wp1, wp + kh * 512);
        lds128(ws0, ws1, ws + kh * 512);
        #pragma unroll
        for (int r = 0; r < 12; r++) {
            ull b0, b1;                                  // (x,x),(x',x') bc
            lds128(b0, b1, ROWS + r * 512 + kh * 16);
            aP[r] = f2fma(b1, wp1, f2fma(b0, wp0, aP[r]));
            aS[r] = f2fma(b1, ws1, f2fma(b0, ws0, aS[r]));
        }
    }

    // neigh = max over 6 agents of relu(p); relu folded via 0-init
    #pragma unroll
    for (int g = 0; g < 2; g++) {
        float mx = 0.f, my = 0.f;
        #pragma unroll
        for (int r = g * 6; r < g * 6 + 6; r++) {
            float2 p = upk(aP[r]);
            mx = fmaxf(mx, p.x); my = fmaxf(my, p.y);
        }
        sts128(NB + g * 512 + lane * 16, mx, mx, my, my);
    }
    __syncwarp();

    // nn = neigh @ Wn (interleaved layout streamed from g_wk, L1-resident)
    ull nn0 = 0ull, nn1 = 0ull;
    const float* wnp = wng + lane * 4;
    #pragma unroll 4
    for (int kh = 0; kh < 32; kh++) {
        ull w0, w1;
        ldg2u64(w0, w1, wnp + kh * 128);
        ull b0, b1;
        lds128(b0, b1, NB + kh * 16);
        nn0 = f2fma(b1, w1, f2fma(b0, w0, nn0));
        lds128(b0, b1, NB + 512 + kh * 16);
        nn1 = f2fma(b1, w1, f2fma(b0, w0, nn1));
    }
    ull bbv = *(const ull*)(misc + bB + 2 * lane);
    float2 n0 = upk(f2add(nn0, bbv));
    float2 n1 = upk(f2add(nn1, bbv));

    if (FIRST) {
        #pragma unroll
        for (int r = 0; r < 12; r++) {
            float2 s = upk(aS[r]);
            float nx = (r < 6) ? n0.x : n1.x, ny = (r < 6) ? n0.y : n1.y;
            float v0 = tanhf(s.x + nx);
            float v1 = tanhf(s.y + ny);
            sts128(ROWS + r * 512 + lane * 16, v0, v0, v1, v1);
        }
    } else {
        #pragma unroll
        for (int g = 0; g < 2; g++) {
            ull t = aS[g * 6];
            #pragma unroll
            for (int r = g * 6 + 1; r < g * 6 + 6; r++) t = f2add(t, aS[r]);
            float2 s = upk(t);
            float v0 = s.x * (1.f / 6.f) + (g ? n1.x : n0.x);
            float v1 = s.y * (1.f / 6.f) + (g ? n1.y : n0.y);
            sts128(RESs + g * 512 + lane * 16, v0, v0, v1, v1);
        }
    }
    __syncwarp();
}

__global__ void __launch_bounds__(THREADS, 1) gnn_kernel(Params P)
{
    cp_i(smem + OFF_WP1, P.Wp1);
    cp_i(smem + OFF_WS1, P.Ws1);
    cp_i(smem + OFF_WP2, P.Wp2);
    cp_i(smem + OFF_WS2, P.Ws2);
    cp4(smem + OFF_MISC +   0, P.bp1, 64);
    cp4(smem + OFF_MISC +  64, P.b1,  64);
    cp4(smem + OFF_MISC + 128, P.bp2, 64);
    cp4(smem + OFF_MISC + 192, P.b2,  64);
    cp4(smem + OFF_MISC + 256, P.Mb1, 128);
    cp4(smem + OFF_MISC + 384, P.Mb2, 128);
    cp4(smem + OFF_MISC + 512, P.Mb3, 128);
    cp4(smem + OFF_MISC + 640, P.MW4, 256);
    cp4(smem + OFF_MISC + 896, P.Mb4, 4);
    __syncthreads();

    const int lane = threadIdx.x & 31;
    const int warp = threadIdx.x >> 5;
    const float* misc = smem + OFF_MISC;

    const unsigned sb  = (unsigned)__cvta_generic_to_shared(smem);
    const unsigned wsA = sb + (OFF_WS_ + warp * WARP_WS) * 4;
    const unsigned OBS = wsA;                  // dup [12][128] (6144 B)
    const unsigned XA  = wsA;                  // alias: dup [4][128] (2048 B)
    const unsigned XB  = wsA + 2048;           // alias: dup [4][128]
    const unsigned NB  = wsA + 1536 * 4;       // dup [2][128]
    const unsigned RES = wsA + 1792 * 4;       // ring dup [4][128]
    const unsigned WP1 = sb + OFF_WP1 * 4, WS1 = sb + OFF_WS1 * 4;
    const unsigned WP2 = sb + OFF_WP2 * 4, WS2 = sb + OFF_WS2 * 4;

    const int wg   = blockIdx.x * WARPS + warp;
    const int base = wg * P.ch4;
    const int iters = P.ch4 >> 1;

    for (int j = 0; j < iters; j++) {
        const int g0 = base + 2 * j, g1 = g0 + 1;

        // stage obs duplicated: float2 (a,b) -> (a,a,b,b)
        {
            const float2* s0 = (const float2*)(P.obs + (size_t)g0 * 384);
            const float2* s1 = (const float2*)(P.obs + (size_t)g1 * 384);
            const float2 z = make_float2(0.f, 0.f);
            #pragma unroll
            for (int i = 0; i < 6; i++) {
                int m = lane + 32 * i;
                float2 a = (g0 < G_TOT) ? s0[m] : z;
                float2 b = (g1 < G_TOT) ? s1[m] : z;
                sts128(OBS + m * 16, a.x, a.x, a.y, a.y);
                sts128(OBS + 3072 + m * 16, b.x, b.x, b.y, b.y);
            }
        }
        __syncwarp();

        const unsigned RESs = RES + (j & 1) * 1024;
        conv2g<true >(OBS, NB, RESs, WP1, WS1, g_wk,        misc,   0,  64, lane);
        conv2g<false>(OBS, NB, RESs, WP2, WS2, g_wk + 4096, misc, 128, 192, lane);

        if (j & 1) {
            // ---- MLP on 4 ring groups ----
            const int gbase = base + 2 * (j - 1);
            float hA[4], hB[4];

            #pragma unroll
            for (int t = 0; t < 2; t++) {
                // L1: RES -> XA
                ull a1[4];
                ull b1v = *(const ull*)(misc + 256 + t * 64 + 2 * lane);
                #pragma unroll
                for (int g = 0; g < 4; g++) a1[g] = b1v;
                const float* w1p = g_wk + (2 + t) * 4096 + lane * 4;
                #pragma unroll 4
                for (int kh = 0; kh < 32; kh++) {
                    ull w0, w1;
                    ldg2u64(w0, w1, w1p + kh * 128);
                    #pragma unroll
                    for (int g = 0; g < 4; g++) {
                        ull b0, b1;
                        lds128(b0, b1, RES + g * 512 + kh * 16);
                        a1[g] = f2fma(b1, w1, f2fma(b0, w0, a1[g]));
                    }
                }
                #pragma unroll
                for (int g = 0; g < 4; g++) {
                    float2 v = upk(a1[g]);
                    float r0 = fmaxf(v.x, 0.f), r1 = fmaxf(v.y, 0.f);
                    sts128(XA + g * 512 + lane * 16, r0, r0, r1, r1);
                }
                __syncwarp();

                // L2: XA -> XB
                ull a2[4];
                ull b2v = *(const ull*)(misc + 384 + t * 64 + 2 * lane);
                #pragma unroll
                for (int g = 0; g < 4; g++) a2[g] = b2v;
                const float* w2p = g_wk + (4 + t) * 4096 + lane * 4;
                #pragma unroll 4
                for (int kh = 0; kh < 32; kh++) {
                    ull w0, w1;
                    ldg2u64(w0, w1, w2p + kh * 128);
                    #pragma unroll
                    for (int g = 0; g < 4; g++) {
                        ull b0, b1;
                        lds128(b0, b1, XA + g * 512 + kh * 16);
                        a2[g] = f2fma(b1, w1, f2fma(b0, w0, a2[g]));
                    }
                }
                #pragma unroll
                for (int g = 0; g < 4; g++) {
                    float2 v = upk(a2[g]);
                    float r0 = fmaxf(v.x, 0.f), r1 = fmaxf(v.y, 0.f);
                    sts128(XB + g * 512 + lane * 16, r0, r0, r1, r1);
                }
                __syncwarp();

                // L3: XB -> regs, then head directly from registers
                ull a3[4];
                ull b3v = *(const ull*)(misc + 512 + t * 64 + 2 * lane);
                #pragma unroll
                for (int g = 0; g < 4; g++) a3[g] = b3v;
                const float* w3p = g_wk + (6 + t) * 4096 + lane * 4;
                #pragma unroll 4
                for (int kh = 0; kh < 32; kh++) {
                    ull w0, w1;
                    ldg2u64(w0, w1, w3p + kh * 128);
                    #pragma unroll
                    for (int g = 0; g < 4; g++) {
                        ull b0, b1;
                        lds128(b0, b1, XB + g * 512 + kh * 16);
                        a3[g] = f2fma(b1, w1, f2fma(b0, w0, a3[g]));
                    }
                }
                float4 w4 = *(const float4*)(misc + 640 + t * 128 + 4 * lane);
                float b40 = misc[896 + t * 2], b41 = misc[896 + t * 2 + 1];
                #pragma unroll
                for (int g = 0; g < 4; g++) {
                    float2 v = upk(a3[g]);
                    float v0 = fmaxf(v.x, 0.f), v1 = fmaxf(v.y, 0.f);
                    float s0 = v0 * w4.x + v1 * w4.z;
                    float s1 = v0 * w4.y + v1 * w4.w;
                    #pragma unroll
                    for (int off = 16; off; off >>= 1) {
                        s0 += __shfl_xor_sync(0xffffffffu, s0, off);
                        s1 += __shfl_xor_sync(0xffffffffu, s1, off);
                    }
                    float r0 = tanhf(s0 + b40), r1 = tanhf(s1 + b41);
                    if (t == 0) { hA[g] = r0; hB[g] = r1; }
                    else {
                        int go = gbase + g;
                        if (go < G_TOT && lane < 3) {
                            float A = hA[g], B = hB[g];
                            float4 v4 = (lane < 2) ? make_float4(A, B, A, B)
                                                   : make_float4(A, B, r0, r1);
                            ((float4*)(P.out + (size_t)go * 12))[lane] = v4;
                        }
                    }
                }
                __syncwarp();   // XA/XB reused by t=1
            }
        }
    }
}

extern "C" void kernel_launch(void* const* d_in, const int* in_sizes, int n_in,
                              void* d_out, int out_size)
{
    (void)in_sizes; (void)n_in; (void)out_size;
    Params P;
    P.obs = (const float*)d_in[0];
    P.Wp1 = (const float*)d_in[1];  P.bp1 = (const float*)d_in[2];
    P.Ws1 = (const float*)d_in[3];  P.Wn1 = (const float*)d_in[4];
    P.b1  = (const float*)d_in[5];
    P.Wp2 = (const float*)d_in[6];  P.bp2 = (const float*)d_in[7];
    P.Ws2 = (const float*)d_in[8];  P.Wn2 = (const float*)d_in[9];
    P.b2  = (const float*)d_in[10];
    P.MW1 = (const float*)d_in[11]; P.Mb1 = (const float*)d_in[12];
    P.MW2 = (const float*)d_in[13]; P.Mb2 = (const float*)d_in[14];
    P.MW3 = (const float*)d_in[15]; P.Mb3 = (const float*)d_in[16];
    P.MW4 = (const float*)d_in[17]; P.Mb4 = (const float*)d_in[18];
    P.out = (float*)d_out;

    int dev = 0, nsm = 148;
    cudaGetDevice(&dev);
    cudaDeviceGetAttribute(&nsm, cudaDevAttrMultiProcessorCount, dev);

    // groups per warp, multiple of 4 (MLP ring size)
    int nw = nsm * WARPS;
    int ch4 = ((G_TOT + nw * 4 - 1) / (nw * 4)) * 4;
    P.ch4 = ch4;

    prep_kernel<<<(8 * 1024 + 255) / 256, 256>>>(P.Wn1, P.Wn2, P.MW1, P.MW2, P.MW3);

    cudaFuncSetAttribute(gnn_kernel, cudaFuncAttributeMaxDynamicSharedMemorySize,
                         SMEM_BYTES);
    gnn_kernel<<<nsm, THREADS, SMEM_BYTES>>>(P);
}

// round 10
// speedup vs baseline: 1.3143x; 1.3143x over previous
#include <cuda_runtime.h>

// ---------------------------------------------------------------------------
// GNNMLP fused kernel, round 9 = round 8 + group-1 staging offset fix.
//  * ONLY 8-byte loads/stores in hot loops (plain C++ derefs -> LDS.64/LDG.64).
//    R0/R4 proved this keeps ptxas register allocation clean (fma-busy ~451us);
//    v2.u64/v4 quad-constrained asm (R5/R6) inflated fma-pipe by 1.6x.
//  * dup activation layout (x,x): 8B broadcast = packed f32x2 operand, 0 MOVs.
//  * natural row-major weights: lane-strided 8B load = (w[k][2l],w[k][2l+1]).
//    -> works directly on the INPUT tensors, no prep kernel, no interleave.
//  * conv: 2 groups/warp (24 acc pairs); MLP: 6-group ring, head from regs.
//  * R8 bug: group-1 obs staged at float2 index 768 (6144B) instead of 384
//    (3072B = row 6), overflowing OBS into NB/RES. Fixed here.
// ---------------------------------------------------------------------------

#define G_TOT   131072
#define THREADS 384
#define WARPS   12
#define RING    6

typedef unsigned long long ull;

// ---- packed f32x2 helpers --------------------------------------------------
__device__ __forceinline__ float2 upk(ull v) {
    float2 r; asm("mov.b64 {%0,%1}, %2;" : "=f"(r.x), "=f"(r.y) : "l"(v)); return r;
}
__device__ __forceinline__ ull f2fma(ull a, ull b, ull c) {
    ull d; asm("fma.rn.f32x2 %0, %1, %2, %3;" : "=l"(d) : "l"(a), "l"(b), "l"(c));
    return d;
}
__device__ __forceinline__ ull f2add(ull a, ull b) {
    ull d; asm("add.rn.f32x2 %0, %1, %2;" : "=l"(d) : "l"(a), "l"(b)); return d;
}

// ---- SMEM layout (float offsets) ------------------------------------------
#define OFF_WP1  0
#define OFF_WS1  4096
#define OFF_WP2  8192
#define OFF_WS2  12288
#define OFF_MISC 16384
//  MISC: +0 bp1 +64 b1 +128 bp2 +192 b2 +256 Mb1[128] +384 Mb2[128]
//        +512 Mb3[128] +640 MW4[2][64][2]=256 +896 Mb4[4]
#define OFF_WS_  17408
#define WARP_WS  2560   // OBS dup[12][128]=1536 | NB dup[2][128]=256 | RES dup[6][128]=768
#define SMEM_FLOATS (OFF_WS_ + WARPS * WARP_WS)   // 48128
#define SMEM_BYTES  (SMEM_FLOATS * 4)             // 192512 < 232448

struct Params {
    const float *obs, *Wp1, *bp1, *Ws1, *Wn1, *b1;
    const float *Wp2, *bp2, *Ws2, *Wn2, *b2;
    const float *MW1, *Mb1, *MW2, *Mb2, *MW3, *Mb3, *MW4, *Mb4;
    float *out;
    int ch;          // groups per warp (multiple of RING)
};

extern __shared__ float smem[];

__device__ __forceinline__ void cp4(float* dst, const float* src, int n) {
    for (int i = threadIdx.x; i < (n >> 2); i += THREADS)
        ((float4*)dst)[i] = ((const float4*)src)[i];
}

// ---- one SAGE-pool conv, 2 groups (12 dup rows) ----------------------------
// rows: dup [12][64 ull]; lane owns output cols {2l,2l+1}.
template<bool FIRST>
__device__ __forceinline__ void conv2g(ull* rows, ull* nb, ull* resv,
                                       const float* sWp, const float* sWs,
                                       const float* __restrict__ gWn,
                                       const float* misc, int bP, int bB, int lane)
{
    ull aP[12], aS[12];
    ull bpv = *(const ull*)(misc + bP + 2 * lane);
    #pragma unroll
    for (int r = 0; r < 12; r++) { aP[r] = bpv; aS[r] = 0ull; }

    const ull* wp = (const ull*)sWp + lane;     // W[k][2l..2l+1] at k*32+l
    const ull* ws = (const ull*)sWs + lane;

    #pragma unroll 4
    for (int k = 0; k < 64; k++) {
        ull w1 = wp[k * 32];
        ull w2 = ws[k * 32];
        #pragma unroll
        for (int r = 0; r < 12; r++) {
            ull x = rows[r * 64 + k];            // (x_k,x_k) broadcast, 8B
            aP[r] = f2fma(x, w1, aP[r]);
            aS[r] = f2fma(x, w2, aS[r]);
        }
    }

    // neigh = max over 6 agents of relu(p); relu folded via 0-init
    #pragma unroll
    for (int g = 0; g < 2; g++) {
        float mx = 0.f, my = 0.f;
        #pragma unroll
        for (int r = g * 6; r < g * 6 + 6; r++) {
            float2 p = upk(aP[r]);
            mx = fmaxf(mx, p.x); my = fmaxf(my, p.y);
        }
        float2* d = (float2*)(nb + g * 64);
        d[2 * lane]     = make_float2(mx, mx);   // dup store, 8B
        d[2 * lane + 1] = make_float2(my, my);
    }
    __syncwarp();

    // nn = neigh @ Wn  (Wn natural row-major, streamed from global)
    ull nn0 = 0ull, nn1 = 0ull;
    const ull* wn = (const ull*)gWn + lane;
    #pragma unroll 4
    for (int k = 0; k < 64; k++) {
        ull w  = wn[k * 32];
        ull x0 = nb[k];
        ull x1 = nb[64 + k];
        nn0 = f2fma(x0, w, nn0);
        nn1 = f2fma(x1, w, nn1);
    }
    ull bbv = *(const ull*)(misc + bB + 2 * lane);
    float2 n0 = upk(f2add(nn0, bbv));
    float2 n1 = upk(f2add(nn1, bbv));

    if (FIRST) {
        #pragma unroll
        for (int r = 0; r < 12; r++) {
            float2 s = upk(aS[r]);
            float nx = (r < 6) ? n0.x : n1.x, ny = (r < 6) ? n0.y : n1.y;
            float v0 = tanhf(s.x + nx);
            float v1 = tanhf(s.y + ny);
            float2* d = (float2*)(rows + r * 64);
            d[2 * lane]     = make_float2(v0, v0);
            d[2 * lane + 1] = make_float2(v1, v1);
        }
    } else {
        #pragma unroll
        for (int g = 0; g < 2; g++) {
            ull t = aS[g * 6];
            #pragma unroll
            for (int r = g * 6 + 1; r < g * 6 + 6; r++) t = f2add(t, aS[r]);
            float2 s = upk(t);
            float v0 = s.x * (1.f / 6.f) + (g ? n1.x : n0.x);
            float v1 = s.y * (1.f / 6.f) + (g ? n1.y : n0.y);
            float2* d = (float2*)(resv + g * 64);
            d[2 * lane]     = make_float2(v0, v0);
            d[2 * lane + 1] = make_float2(v1, v1);
        }
    }
    __syncwarp();
}

__global__ void __launch_bounds__(THREADS, 1) gnn_kernel(Params P)
{
    cp4(smem + OFF_WP1, P.Wp1, 4096);
    cp4(smem + OFF_WS1, P.Ws1, 4096);
    cp4(smem + OFF_WP2, P.Wp2, 4096);
    cp4(smem + OFF_WS2, P.Ws2, 4096);
    cp4(smem + OFF_MISC +   0, P.bp1, 64);
    cp4(smem + OFF_MISC +  64, P.b1,  64);
    cp4(smem + OFF_MISC + 128, P.bp2, 64);
    cp4(smem + OFF_MISC + 192, P.b2,  64);
    cp4(smem + OFF_MISC + 256, P.Mb1, 128);
    cp4(smem + OFF_MISC + 384, P.Mb2, 128);
    cp4(smem + OFF_MISC + 512, P.Mb3, 128);
    cp4(smem + OFF_MISC + 640, P.MW4, 256);
    cp4(smem + OFF_MISC + 896, P.Mb4, 4);
    __syncthreads();

    const int lane = threadIdx.x & 31;
    const int warp = threadIdx.x >> 5;
    const float* misc = smem + OFF_MISC;

    float* wsf = smem + OFF_WS_ + warp * WARP_WS;
    ull* OBS = (ull*)wsf;                  // dup [12][64 ull]
    ull* NB  = (ull*)(wsf + 1536);         // dup [2][64 ull]
    ull* RES = (ull*)(wsf + 1792);         // ring dup [6][64 ull]
    ull* XA0 = OBS;                        // alias: dup [6][64 ull]
    ull* XA1 = OBS + 6 * 64;               // alias: dup [6][64 ull]
    ull* XB  = RES;                        // alias: RES dead after MLP L1
    const float* sWP1 = smem + OFF_WP1, *sWS1 = smem + OFF_WS1;
    const float* sWP2 = smem + OFF_WP2, *sWS2 = smem + OFF_WS2;

    const int wg   = blockIdx.x * WARPS + warp;
    const int base = wg * P.ch;
    const int iters = P.ch >> 1;

    for (int j = 0; j < iters; j++) {
        const int g0 = base + 2 * j, g1 = g0 + 1;

        // stage obs duplicated: (a,b) -> (a,a),(b,b)
        // group 0 rows 0..5 start at float2 index 0; group 1 rows 6..11 start
        // at float2 index 384 (= 6 rows * 64 ull) -- R8 wrote 768 here (bug).
        {
            const float2* s0 = (const float2*)(P.obs + (size_t)g0 * 384);
            const float2* s1 = (const float2*)(P.obs + (size_t)g1 * 384);
            const float2 z = make_float2(0.f, 0.f);
            float2* d = (float2*)OBS;
            #pragma unroll
            for (int i = 0; i < 6; i++) {
                int m = lane + 32 * i;
                float2 a = (g0 < G_TOT) ? s0[m] : z;
                float2 b = (g1 < G_TOT) ? s1[m] : z;
                d[2 * m]           = make_float2(a.x, a.x);
                d[2 * m + 1]       = make_float2(a.y, a.y);
                d[384 + 2 * m]     = make_float2(b.x, b.x);
                d[384 + 2 * m + 1] = make_float2(b.y, b.y);
            }
        }
        __syncwarp();

        ull* RESs = RES + (j % 3) * 128;     // 2 groups per slot-pair
        conv2g<true >(OBS, NB, RESs, sWP1, sWS1, P.Wn1, misc,   0,  64, lane);
        conv2g<false>(OBS, NB, RESs, sWP2, sWS2, P.Wn2, misc, 128, 192, lane);

        if (j % 3 == 2) {
            // ---- MLP on RING=6 groups ----
            const int gbase = base + 2 * (j - 2);

            // L1 fused over both types: RES -> XA0/XA1
            ull a0[6], a1[6];
            ull b10 = *(const ull*)(misc + 256 + 2 * lane);
            ull b11 = *(const ull*)(misc + 256 + 64 + 2 * lane);
            #pragma unroll
            for (int g = 0; g < 6; g++) { a0[g] = b10; a1[g] = b11; }
            {
                const ull* w0p = (const ull*)P.MW1 + lane;
                const ull* w1p = (const ull*)(P.MW1 + 4096) + lane;
                #pragma unroll 4
                for (int k = 0; k < 64; k++) {
                    ull w0 = w0p[k * 32];
                    ull w1 = w1p[k * 32];
                    #pragma unroll
                    for (int g = 0; g < 6; g++) {
                        ull x = RES[g * 64 + k];
                        a0[g] = f2fma(x, w0, a0[g]);
                        a1[g] = f2fma(x, w1, a1[g]);
                    }
                }
            }
            __syncwarp();          // RES reads done; XA0/XA1 alias OBS (dead)
            #pragma unroll
            for (int g = 0; g < 6; g++) {
                float2 v = upk(a0[g]);
                float2* d = (float2*)(XA0 + g * 64);
                d[2 * lane]     = make_float2(fmaxf(v.x, 0.f), fmaxf(v.x, 0.f));
                d[2 * lane + 1] = make_float2(fmaxf(v.y, 0.f), fmaxf(v.y, 0.f));
                v = upk(a1[g]);
                d = (float2*)(XA1 + g * 64);
                d[2 * lane]     = make_float2(fmaxf(v.x, 0.f), fmaxf(v.x, 0.f));
                d[2 * lane + 1] = make_float2(fmaxf(v.y, 0.f), fmaxf(v.y, 0.f));
            }
            __syncwarp();

            float hA[6], hB[6];
            #pragma unroll
            for (int t = 0; t < 2; t++) {
                const ull* XAt = t ? XA1 : XA0;

                // L2: XA_t -> XB  (XB aliases RES, dead after L1)
                ull a2[6];
                ull b2v = *(const ull*)(misc + 384 + t * 64 + 2 * lane);
                #pragma unroll
                for (int g = 0; g < 6; g++) a2[g] = b2v;
                {
                    const ull* w2p = (const ull*)(P.MW2 + t * 4096) + lane;
                    #pragma unroll 4
                    for (int k = 0; k < 64; k++) {
                        ull w = w2p[k * 32];
                        #pragma unroll
                        for (int g = 0; g < 6; g++)
                            a2[g] = f2fma(XAt[g * 64 + k], w, a2[g]);
                    }
                }
                #pragma unroll
                for (int g = 0; g < 6; g++) {
                    float2 v = upk(a2[g]);
                    float2* d = (float2*)(XB + g * 64);
                    d[2 * lane]     = make_float2(fmaxf(v.x, 0.f), fmaxf(v.x, 0.f));
                    d[2 * lane + 1] = make_float2(fmaxf(v.y, 0.f), fmaxf(v.y, 0.f));
                }
                __syncwarp();

                // L3: XB -> regs, head directly from registers
                ull a3[6];
                ull b3v = *(const ull*)(misc + 512 + t * 64 + 2 * lane);
                #pragma unroll
                for (int g = 0; g < 6; g++) a3[g] = b3v;
                {
                    const ull* w3p = (const ull*)(P.MW3 + t * 4096) + lane;
                    #pragma unroll 4
                    for (int k = 0; k < 64; k++) {
                        ull w = w3p[k * 32];
                        #pragma unroll
                        for (int g = 0; g < 6; g++)
                            a3[g] = f2fma(XB[g * 64 + k], w, a3[g]);
                    }
                }
                __syncwarp();      // XB reads done before t=1 overwrites

                float4 w4 = *(const float4*)(misc + 640 + t * 128 + 4 * lane);
                float b40 = misc[896 + t * 2], b41 = misc[896 + t * 2 + 1];
                #pragma unroll
                for (int g = 0; g < 6; g++) {
                    float2 v = upk(a3[g]);
                    float v0 = fmaxf(v.x, 0.f), v1 = fmaxf(v.y, 0.f);
                    float s0 = v0 * w4.x + v1 * w4.z;
                    float s1 = v0 * w4.y + v1 * w4.w;
                    #pragma unroll
                    for (int off = 16; off; off >>= 1) {
                        s0 += __shfl_xor_sync(0xffffffffu, s0, off);
                        s1 += __shfl_xor_sync(0xffffffffu, s1, off);
                    }
                    float r0 = tanhf(s0 + b40), r1 = tanhf(s1 + b41);
                    if (t == 0) { hA[g] = r0; hB[g] = r1; }
                    else {
                        int go = gbase + g;
                        if (go < G_TOT && lane < 3) {
                            float A = hA[g], B = hB[g];
                            float4 v4 = (lane < 2) ? make_float4(A, B, A, B)
                                                   : make_float4(A, B, r0, r1);
                            ((float4*)(P.out + (size_t)go * 12))[lane] = v4;
                        }
                    }
                }
            }
            __syncwarp();          // workspace reused by next conv iteration
        }
    }
}

extern "C" void kernel_launch(void* const* d_in, const int* in_sizes, int n_in,
                              void* d_out, int out_size)
{
    (void)in_sizes; (void)n_in; (void)out_size;
    Params P;
    P.obs = (const float*)d_in[0];
    P.Wp1 = (const float*)d_in[1];  P.bp1 = (const float*)d_in[2];
    P.Ws1 = (const float*)d_in[3];  P.Wn1 = (const float*)d_in[4];
    P.b1  = (const float*)d_in[5];
    P.Wp2 = (const float*)d_in[6];  P.bp2 = (const float*)d_in[7];
    P.Ws2 = (const float*)d_in[8];  P.Wn2 = (const float*)d_in[9];
    P.b2  = (const float*)d_in[10];
    P.MW1 = (const float*)d_in[11]; P.Mb1 = (const float*)d_in[12];
    P.MW2 = (const float*)d_in[13]; P.Mb2 = (const float*)d_in[14];
    P.MW3 = (const float*)d_in[15]; P.Mb3 = (const float*)d_in[16];
    P.MW4 = (const float*)d_in[17]; P.Mb4 = (const float*)d_in[18];
    P.out = (float*)d_out;

    int dev = 0, nsm = 148;
    cudaGetDevice(&dev);
    cudaDeviceGetAttribute(&nsm, cudaDevAttrMultiProcessorCount, dev);

    int nw = nsm * WARPS;
    int ch = ((G_TOT + nw * RING - 1) / (nw * RING)) * RING;
    P.ch = ch;

    cudaFuncSetAttribute(gnn_kernel, cudaFuncAttributeMaxDynamicSharedMemorySize,
                         SMEM_BYTES);
    gnn_kernel<<<nsm, THREADS, SMEM_BYTES>>>(P);
}

// round 11
// speedup vs baseline: 1.6543x; 1.2587x over previous
#include <cuda_runtime.h>

// ---------------------------------------------------------------------------
// GNNMLP fused kernel, round 10.
//  * dup activation layout; broadcasts upgraded to 16B lds128 -> 1 wavefront
//    feeds TWO k-steps (R4 proved shared-quad loads are codegen-clean).
//  * weights: plain C++ b64 derefs (LDS.64 smem / LDG.64 global) - the
//    R0/R4/R9-proven clean idiom. No global quads, no prep kernel.
//  * conv: 2 groups/warp; MLP: 4-group ring; head from registers.
//  * 16 warps / 512 threads (occ 25%), smem 217KB.
// ---------------------------------------------------------------------------

#define G_TOT   131072
#define THREADS 512
#define WARPS   16
#define RING    4

typedef unsigned long long ull;

// ---- packed f32x2 helpers --------------------------------------------------
__device__ __forceinline__ float2 upk(ull v) {
    float2 r; asm("mov.b64 {%0,%1}, %2;" : "=f"(r.x), "=f"(r.y) : "l"(v)); return r;
}
__device__ __forceinline__ ull f2fma(ull a, ull b, ull c) {
    ull d; asm("fma.rn.f32x2 %0, %1, %2, %3;" : "=l"(d) : "l"(a), "l"(b), "l"(c));
    return d;
}
__device__ __forceinline__ ull f2add(ull a, ull b) {
    ull d; asm("add.rn.f32x2 %0, %1, %2;" : "=l"(d) : "l"(a), "l"(b)); return d;
}
__device__ __forceinline__ void lds128(ull& a, ull& b, unsigned addr) {
    asm volatile("ld.shared.v2.u64 {%0,%1}, [%2];" : "=l"(a), "=l"(b) : "r"(addr));
}
__device__ __forceinline__ void sts128(unsigned a, float x, float y, float z, float w) {
    asm volatile("st.shared.v4.f32 [%0], {%1,%2,%3,%4};"
                 :: "r"(a), "f"(x), "f"(y), "f"(z), "f"(w));
}

// ---- SMEM layout (float offsets) ------------------------------------------
#define OFF_WP1  0
#define OFF_WS1  4096
#define OFF_WP2  8192
#define OFF_WS2  12288
#define OFF_MISC 16384
//  MISC: +0 bp1 +64 b1 +128 bp2 +192 b2 +256 Mb1[128] +384 Mb2[128]
//        +512 Mb3[128] +640 MW4[2][64][2]=256 +896 Mb4[4]
#define OFF_WS_  17408
#define WARP_WS  2304   // OBS dup[12][128]=1536 | NB dup[2][128]=256 | RES dup[4][128]=512
#define SMEM_FLOATS (OFF_WS_ + WARPS * WARP_WS)   // 54272
#define SMEM_BYTES  (SMEM_FLOATS * 4)             // 217088 < 232448

struct Params {
    const float *obs, *Wp1, *bp1, *Ws1, *Wn1, *b1;
    const float *Wp2, *bp2, *Ws2, *Wn2, *b2;
    const float *MW1, *Mb1, *MW2, *Mb2, *MW3, *Mb3, *MW4, *Mb4;
    float *out;
    int ch;          // groups per warp (multiple of RING)
};

extern __shared__ float smem[];

__device__ __forceinline__ void cp4(float* dst, const float* src, int n) {
    for (int i = threadIdx.x; i < (n >> 2); i += THREADS)
        ((float4*)dst)[i] = ((const float4*)src)[i];
}

// ---- one SAGE-pool conv, 2 groups (12 dup rows) ----------------------------
// ROWS (byte addr): dup [12][128 floats]; row r at +r*512B, k-pair kh at +kh*16B.
// Weights: smem ull* lane-strided, W[k] pair at index k*32. Lane owns cols {2l,2l+1}.
template<bool FIRST>
__device__ __forceinline__ void conv2g(unsigned ROWS, unsigned NB, unsigned RESb,
                                       const ull* wp, const ull* ws,
                                       const ull* __restrict__ wn,
                                       const float* misc, int bP, int bB, int lane)
{
    ull aP[12], aS[12];
    ull bpv = *(const ull*)(misc + bP + 2 * lane);
    #pragma unroll
    for (int r = 0; r < 12; r++) { aP[r] = bpv; aS[r] = 0ull; }

    #pragma unroll 4
    for (int kh = 0; kh < 32; kh++) {
        ull wp0 = wp[(2 * kh) * 32];         // LDS.64 lane-strided
        ull wp1 = wp[(2 * kh + 1) * 32];
        ull ws0 = ws[(2 * kh) * 32];
        ull ws1 = ws[(2 * kh + 1) * 32];
        #pragma unroll
        for (int r = 0; r < 12; r++) {
            ull b0, b1;                       // (x_k,x_k),(x_k1,x_k1) 16B bc
            lds128(b0, b1, ROWS + r * 512 + kh * 16);
            aP[r] = f2fma(b1, wp1, f2fma(b0, wp0, aP[r]));
            aS[r] = f2fma(b1, ws1, f2fma(b0, ws0, aS[r]));
        }
    }

    // neigh = max over 6 agents of relu(p); relu folded via 0-init
    #pragma unroll
    for (int g = 0; g < 2; g++) {
        float mx = 0.f, my = 0.f;
        #pragma unroll
        for (int r = g * 6; r < g * 6 + 6; r++) {
            float2 p = upk(aP[r]);
            mx = fmaxf(mx, p.x); my = fmaxf(my, p.y);
        }
        sts128(NB + g * 512 + lane * 16, mx, mx, my, my);
    }
    __syncwarp();

    // nn = neigh @ Wn  (Wn natural row-major, streamed from global as LDG.64)
    ull nn0 = 0ull, nn1 = 0ull;
    #pragma unroll 4
    for (int kh = 0; kh < 32; kh++) {
        ull w0 = wn[(2 * kh) * 32];
        ull w1 = wn[(2 * kh + 1) * 32];
        ull b0, b1;
        lds128(b0, b1, NB + kh * 16);
        nn0 = f2fma(b1, w1, f2fma(b0, w0, nn0));
        lds128(b0, b1, NB + 512 + kh * 16);
        nn1 = f2fma(b1, w1, f2fma(b0, w0, nn1));
    }
    ull bbv = *(const ull*)(misc + bB + 2 * lane);
    float2 n0 = upk(f2add(nn0, bbv));
    float2 n1 = upk(f2add(nn1, bbv));

    if (FIRST) {
        #pragma unroll
        for (int r = 0; r < 12; r++) {
            float2 s = upk(aS[r]);
            float nx = (r < 6) ? n0.x : n1.x, ny = (r < 6) ? n0.y : n1.y;
            float v0 = tanhf(s.x + nx);
            float v1 = tanhf(s.y + ny);
            sts128(ROWS + r * 512 + lane * 16, v0, v0, v1, v1);
        }
    } else {
        #pragma unroll
        for (int g = 0; g < 2; g++) {
            ull t = aS[g * 6];
            #pragma unroll
            for (int r = g * 6 + 1; r < g * 6 + 6; r++) t = f2add(t, aS[r]);
            float2 s = upk(t);
            float v0 = s.x * (1.f / 6.f) + (g ? n1.x : n0.x);
            float v1 = s.y * (1.f / 6.f) + (g ? n1.y : n0.y);
            sts128(RESb + g * 512 + lane * 16, v0, v0, v1, v1);
        }
    }
    __syncwarp();
}

__global__ void __launch_bounds__(THREADS, 1) gnn_kernel(Params P)
{
    cp4(smem + OFF_WP1, P.Wp1, 4096);
    cp4(smem + OFF_WS1, P.Ws1, 4096);
    cp4(smem + OFF_WP2, P.Wp2, 4096);
    cp4(smem + OFF_WS2, P.Ws2, 4096);
    cp4(smem + OFF_MISC +   0, P.bp1, 64);
    cp4(smem + OFF_MISC +  64, P.b1,  64);
    cp4(smem + OFF_MISC + 128, P.bp2, 64);
    cp4(smem + OFF_MISC + 192, P.b2,  64);
    cp4(smem + OFF_MISC + 256, P.Mb1, 128);
    cp4(smem + OFF_MISC + 384, P.Mb2, 128);
    cp4(smem + OFF_MISC + 512, P.Mb3, 128);
    cp4(smem + OFF_MISC + 640, P.MW4, 256);
    cp4(smem + OFF_MISC + 896, P.Mb4, 4);
    __syncthreads();

    const int lane = threadIdx.x & 31;
    const int warp = threadIdx.x >> 5;
    const float* misc = smem + OFF_MISC;

    const unsigned sb  = (unsigned)__cvta_generic_to_shared(smem);
    const unsigned wsb = sb + (OFF_WS_ + warp * WARP_WS) * 4;
    const unsigned OBS = wsb;                 // dup [12][128fl] = 6144 B
    const unsigned XA0 = wsb;                 // alias: dup [4][128] (2048 B)
    const unsigned XA1 = wsb + 2048;          // alias
    const unsigned XB  = wsb + 4096;          // alias (OBS is 6144 B total)
    const unsigned NB  = wsb + 6144;          // dup [2][128] = 1024 B
    const unsigned RES = wsb + 7168;          // ring dup [4][128] = 2048 B

    const ull* sWP1 = (const ull*)(smem + OFF_WP1) + lane;
    const ull* sWS1 = (const ull*)(smem + OFF_WS1) + lane;
    const ull* sWP2 = (const ull*)(smem + OFF_WP2) + lane;
    const ull* sWS2 = (const ull*)(smem + OFF_WS2) + lane;
    const ull* gWN1 = (const ull*)P.Wn1 + lane;
    const ull* gWN2 = (const ull*)P.Wn2 + lane;

    const int wg   = blockIdx.x * WARPS + warp;
    const int base = wg * P.ch;
    const int iters = P.ch >> 1;

    for (int j = 0; j < iters; j++) {
        const int g0 = base + 2 * j, g1 = g0 + 1;

        // stage obs duplicated: float2 (a,b) -> (a,a,b,b); group1 at +3072 B
        {
            const float2* s0 = (const float2*)(P.obs + (size_t)g0 * 384);
            const float2* s1 = (const float2*)(P.obs + (size_t)g1 * 384);
            const float2 z = make_float2(0.f, 0.f);
            #pragma unroll
            for (int i = 0; i < 6; i++) {
                int m = lane + 32 * i;        // m = row*32 + kpair
                float2 a = (g0 < G_TOT) ? s0[m] : z;
                float2 b = (g1 < G_TOT) ? s1[m] : z;
                sts128(OBS + m * 16,        a.x, a.x, a.y, a.y);
                sts128(OBS + 3072 + m * 16, b.x, b.x, b.y, b.y);
            }
        }
        __syncwarp();

        const unsigned RESb = RES + (j & 1) * 1024;   // 2 groups per slot
        conv2g<true >(OBS, NB, RESb, sWP1, sWS1, gWN1, misc,   0,  64, lane);
        conv2g<false>(OBS, NB, RESb, sWP2, sWS2, gWN2, misc, 128, 192, lane);

        if (j & 1) {
            // ---- MLP on RING=4 groups ----
            const int gbase = base + 2 * (j - 1);

            // L1 fused over both types: RES -> XA0/XA1
            ull a0[4], a1[4];
            ull b10 = *(const ull*)(misc + 256 + 2 * lane);
            ull b11 = *(const ull*)(misc + 256 + 64 + 2 * lane);
            #pragma unroll
            for (int g = 0; g < 4; g++) { a0[g] = b10; a1[g] = b11; }
            {
                const ull* __restrict__ wA = (const ull*)P.MW1 + lane;
                const ull* __restrict__ wB = (const ull*)(P.MW1 + 4096) + lane;
                #pragma unroll 4
                for (int kh = 0; kh < 32; kh++) {
                    ull wA0 = wA[(2 * kh) * 32], wA1 = wA[(2 * kh + 1) * 32];
                    ull wB0 = wB[(2 * kh) * 32], wB1 = wB[(2 * kh + 1) * 32];
                    #pragma unroll
                    for (int g = 0; g < 4; g++) {
                        ull b0, b1;
                        lds128(b0, b1, RES + g * 512 + kh * 16);
                        a0[g] = f2fma(b1, wA1, f2fma(b0, wA0, a0[g]));
                        a1[g] = f2fma(b1, wB1, f2fma(b0, wB0, a1[g]));
                    }
                }
            }
            __syncwarp();      // RES reads done; XA0/XA1 alias OBS (dead)
            #pragma unroll
            for (int g = 0; g < 4; g++) {
                float2 v = upk(a0[g]);
                sts128(XA0 + g * 512 + lane * 16,
                       fmaxf(v.x, 0.f), fmaxf(v.x, 0.f),
                       fmaxf(v.y, 0.f), fmaxf(v.y, 0.f));
                v = upk(a1[g]);
                sts128(XA1 + g * 512 + lane * 16,
                       fmaxf(v.x, 0.f), fmaxf(v.x, 0.f),
                       fmaxf(v.y, 0.f), fmaxf(v.y, 0.f));
            }
            __syncwarp();

            float hA[4], hB[4];
            #pragma unroll
            for (int t = 0; t < 2; t++) {
                const unsigned XAt = t ? XA1 : XA0;

                // L2: XA_t -> XB
                ull a2[4];
                ull b2v = *(const ull*)(misc + 384 + t * 64 + 2 * lane);
                #pragma unroll
                for (int g = 0; g < 4; g++) a2[g] = b2v;
                {
                    const ull* __restrict__ w2 = (const ull*)(P.MW2 + t * 4096) + lane;
                    #pragma unroll 4
                    for (int kh = 0; kh < 32; kh++) {
                        ull w0 = w2[(2 * kh) * 32], w1 = w2[(2 * kh + 1) * 32];
                        #pragma unroll
                        for (int g = 0; g < 4; g++) {
                            ull b0, b1;
                            lds128(b0, b1, XAt + g * 512 + kh * 16);
                            a2[g] = f2fma(b1, w1, f2fma(b0, w0, a2[g]));
                        }
                    }
                }
                #pragma unroll
                for (int g = 0; g < 4; g++) {
                    float2 v = upk(a2[g]);
                    sts128(XB + g * 512 + lane * 16,
                           fmaxf(v.x, 0.f), fmaxf(v.x, 0.f),
                           fmaxf(v.y, 0.f), fmaxf(v.y, 0.f));
                }
                __syncwarp();

                // L3: XB -> regs; head directly from registers
                ull a3[4];
                ull b3v = *(const ull*)(misc + 512 + t * 64 + 2 * lane);
                #pragma unroll
                for (int g = 0; g < 4; g++) a3[g] = b3v;
                {
                    const ull* __restrict__ w3 = (const ull*)(P.MW3 + t * 4096) + lane;
                    #pragma unroll 4
                    for (int kh = 0; kh < 32; kh++) {
                        ull w0 = w3[(2 * kh) * 32], w1 = w3[(2 * kh + 1) * 32];
                        #pragma unroll
                        for (int g = 0; g < 4; g++) {
                            ull b0, b1;
                            lds128(b0, b1, XB + g * 512 + kh * 16);
                            a3[g] = f2fma(b1, w1, f2fma(b0, w0, a3[g]));
                        }
                    }
                }
                __syncwarp();  // XB reads done before t=1 overwrites

                float4 w4 = *(const float4*)(misc + 640 + t * 128 + 4 * lane);
                float b40 = misc[896 + t * 2], b41 = misc[896 + t * 2 + 1];
                #pragma unroll
                for (int g = 0; g < 4; g++) {
                    float2 v = upk(a3[g]);
                    float v0 = fmaxf(v.x, 0.f), v1 = fmaxf(v.y, 0.f);
                    float s0 = v0 * w4.x + v1 * w4.z;
                    float s1 = v0 * w4.y + v1 * w4.w;
                    #pragma unroll
                    for (int off = 16; off; off >>= 1) {
                        s0 += __shfl_xor_sync(0xffffffffu, s0, off);
                        s1 += __shfl_xor_sync(0xffffffffu, s1, off);
                    }
                    float r0 = tanhf(s0 + b40), r1 = tanhf(s1 + b41);
                    if (t == 0) { hA[g] = r0; hB[g] = r1; }
                    else {
                        int go = gbase + g;
                        if (go < G_TOT && lane < 3) {
                            float A = hA[g], B = hB[g];
                            float4 v4 = (lane < 2) ? make_float4(A, B, A, B)
                                                   : make_float4(A, B, r0, r1);
                            ((float4*)(P.out + (size_t)go * 12))[lane] = v4;
                        }
                    }
                }
            }
            __syncwarp();      // workspace reused by next conv iteration
        }
    }
}

extern "C" void kernel_launch(void* const* d_in, const int* in_sizes, int n_in,
                              void* d_out, int out_size)
{
    (void)in_sizes; (void)n_in; (void)out_size;
    Params P;
    P.obs = (const float*)d_in[0];
    P.Wp1 = (const float*)d_in[1];  P.bp1 = (const float*)d_in[2];
    P.Ws1 = (const float*)d_in[3];  P.Wn1 = (const float*)d_in[4];
    P.b1  = (const float*)d_in[5];
    P.Wp2 = (const float*)d_in[6];  P.bp2 = (const float*)d_in[7];
    P.Ws2 = (const float*)d_in[8];  P.Wn2 = (const float*)d_in[9];
    P.b2  = (const float*)d_in[10];
    P.MW1 = (const float*)d_in[11]; P.Mb1 = (const float*)d_in[12];
    P.MW2 = (const float*)d_in[13]; P.Mb2 = (const float*)d_in[14];
    P.MW3 = (const float*)d_in[15]; P.Mb3 = (const float*)d_in[16];
    P.MW4 = (const float*)d_in[17]; P.Mb4 = (const float*)d_in[18];
    P.out = (float*)d_out;

    int dev = 0, nsm = 148;
    cudaGetDevice(&dev);
    cudaDeviceGetAttribute(&nsm, cudaDevAttrMultiProcessorCount, dev);

    int nw = nsm * WARPS;
    int ch = ((G_TOT + nw * RING - 1) / (nw * RING)) * RING;
    P.ch = ch;

    cudaFuncSetAttribute(gnn_kernel, cudaFuncAttributeMaxDynamicSharedMemorySize,
                         SMEM_BYTES);
    gnn_kernel<<<nsm, THREADS, SMEM_BYTES>>>(P);
}